// round 11
// baseline (speedup 1.0000x reference)
#include <cuda_runtime.h>
#include <math.h>

// ---------------------------------------------------------------------------
// VQ-VAE forward.  B=16, L=156, P=8, H=W=128, codebook 512x8.
// R11: all activations stored pre-rounded to tf32 (producer epilogue; x gets
//      a one-time rounded copy) -> conv staging becomes pure cp.async.ca
//      double-buffering.  Regs drop -> 4 CTAs/SM.  Numerics bit-identical
//      to R10 (same rna rounding everywhere).
// ---------------------------------------------------------------------------

#define BATCH 16
#define HW    16384   // 128*128

__device__ __forceinline__ float to_tf32(float x) {
    unsigned u; asm("cvt.rna.tf32.f32 %0, %1;" : "=r"(u) : "f"(x));
    return __uint_as_float(u);
}
__device__ __forceinline__ void mma_tf32(float c[4], const float a[4], float2 b) {
    asm volatile("mma.sync.aligned.m16n8k8.row.col.f32.tf32.tf32.f32 "
        "{%0,%1,%2,%3}, {%4,%5,%6,%7}, {%8,%9}, {%0,%1,%2,%3};"
        : "+f"(c[0]), "+f"(c[1]), "+f"(c[2]), "+f"(c[3])
        : "r"(__float_as_uint(a[0])), "r"(__float_as_uint(a[1])),
          "r"(__float_as_uint(a[2])), "r"(__float_as_uint(a[3])),
          "r"(__float_as_uint(b.x)), "r"(__float_as_uint(b.y)));
}
__device__ __forceinline__ void cp16(unsigned dst, const void* src, int srcsize) {
    asm volatile("cp.async.ca.shared.global [%0], [%1], 16, %2;"
                 :: "r"(dst), "l"(src), "r"(srcsize) : "memory");
}

// Static device scratch (allocation-free rule).
__device__ float g_xr[BATCH * 156 * HW];   // tf32-rounded copy of x
__device__ float g_z1[BATCH * 128 * HW];
__device__ float g_z2[BATCH *  64 * HW];
__device__ float g_z3[BATCH *   8 * HW];
__device__ float g_q [BATCH *   8 * HW];
__device__ float g_y1[BATCH *  64 * HW];
__device__ float g_y2[BATCH * 128 * HW];
// tf32 mma weights: [chunk][tap 9][CO_PAD][8 ci-perm], perm p -> ci = (p>>1)+4*(p&1)
__device__ float g_mw_e1[20 * 9 * 128 * 8];
__device__ float g_mw_e2[16 * 9 *  64 * 8];
__device__ float g_mw_e3[ 8 * 9 *  16 * 8];
__device__ float g_mw_d1[ 1 * 9 *  64 * 8];
__device__ float g_mw_d2[ 8 * 9 * 128 * 8];
__device__ float g_mw_d3[16 * 9 * 160 * 8];
__device__ double g_part[256];

// ---------------------------------------------------------------------------
// Weight packing into mma layout (tf32-rna).  transposed=1: ConvTranspose
// (in,out,kh,kw) -> IO swap + spatial flip.
// ---------------------------------------------------------------------------
__device__ void pack_mma(const float* __restrict__ w, float* __restrict__ out,
                         int CIN, int COUT, int CO_PAD, int transposed, int idx) {
    int p     = idx & 7;
    int co    = (idx >> 3) % CO_PAD;
    int tap   = ((idx >> 3) / CO_PAD) % 9;
    int chunk = ((idx >> 3) / CO_PAD) / 9;
    int ci    = chunk * 8 + (p >> 1) + 4 * (p & 1);
    float v = 0.f;
    if (co < COUT && ci < CIN)
        v = transposed ? w[((size_t)ci * COUT + co) * 9 + (8 - tap)]
                       : w[((size_t)co * CIN + ci) * 9 + tap];
    out[idx] = to_tf32(v);
}

__global__ void pack_all(const float* e1w, const float* e2w, const float* e3w,
                         const float* d1w, const float* d2w, const float* d3w,
                         float* me1, float* me2, float* me3,
                         float* md1, float* md2, float* md3) {
    int idx = blockIdx.x * 256 + threadIdx.x;
    if (idx < 184320) { pack_mma(e1w, me1, 156, 128, 128, 0, idx); return; }
    idx -= 184320;
    if (idx < 73728)  { pack_mma(e2w, me2, 128,  64,  64, 0, idx); return; }
    idx -= 73728;
    if (idx < 9216)   { pack_mma(e3w, me3,  64,   8,  16, 0, idx); return; }
    idx -= 9216;
    if (idx < 4608)   { pack_mma(d1w, md1,   8,  64,  64, 1, idx); return; }
    idx -= 4608;
    if (idx < 73728)  { pack_mma(d2w, md2,  64, 128, 128, 1, idx); return; }
    idx -= 73728;
    if (idx < 184320) { pack_mma(d3w, md3, 128, 156, 160, 1, idx); }
}

// one-time tf32 rounding of x (vectorized)
__global__ void round_copy(const float* __restrict__ x, float* __restrict__ xr, int n4) {
    int i = blockIdx.x * 256 + threadIdx.x;
    if (i >= n4) return;
    float4 v = ((const float4*)x)[i];
    v.x = to_tf32(v.x); v.y = to_tf32(v.y);
    v.z = to_tf32(v.z); v.w = to_tf32(v.w);
    ((float4*)xr)[i] = v;
}

__device__ __forceinline__ float apply_act(float v, int ACT) {
    if (ACT == 1) return fmaxf(v, 0.f);
    if (ACT == 2) return 1.f / (1.f + __expf(-v));
    return v;
}

// ---------------------------------------------------------------------------
// tf32 tensor-core 3x3 same-conv (mma.sync m16n8k8).  Block = (n, row h,
// MT co at CO_OFF).  8 warps: wm=warp&3 -> 32-px span, wn=warp>>2 -> MT/2 co.
// Inputs arrive pre-rounded -> staging is pure cp.async.ca double buffering
// (3 x 16B per thread per chunk, one __syncthreads per chunk).  B fragments
// via __ldg from the packed weight tensor (L1-resident, coalesced).
// RND: round stored activation to tf32 (for downstream conv consumers).
// ---------------------------------------------------------------------------
template<int CIN, int COUT, int MT, int ACT, int CO_OFF, int CO_PAD, bool RND>
__global__ __launch_bounds__(256, 4)
void convmma(const float* __restrict__ in, const float* __restrict__ mw,
             const float* __restrict__ bias, float* __restrict__ out) {
    constexpr int CHUNKS = (CIN + 7) / 8;
    constexpr int ROWSTR = 136;
    constexpr int NT     = MT / 16;          // n-tiles per warp
    constexpr int INBUF  = 8 * 3 * ROWSTR;   // 3264 floats per buffer

    __shared__ float s_in[2 * INBUF];

    const int n    = blockIdx.z;
    const int h    = blockIdx.x;
    const int cob0 = CO_OFF + blockIdx.y * MT;
    const int tid  = threadIdx.x;
    const int lane = tid & 31;
    const int warp = tid >> 5;
    const int wm   = warp & 3;
    const int wn   = warp >> 2;
    const int r4   = lane & 3;    // t%4  (k index)
    const int r4h  = lane >> 2;   // t/4  (m/n index)
    const int pxb  = wm * 32;
    const int col  = wn * (MT / 2);

    const float* inN = in + (size_t)n * CIN * HW;

    // zero halo columns of both buffers once (48 rows total)
    if (tid < 48) {
        float* row = s_in + tid * ROWSTR;
        row[0] = 0.f; row[1] = 0.f; row[2] = 0.f; row[3] = 0.f;
        row[132] = 0.f; row[133] = 0.f; row[134] = 0.f; row[135] = 0.f;
    }
    __syncthreads();   // halos visible before first cp.async compute

    // per-thread staging slots: s4 = tid + 256*j, j=0..2
    int sm_off[3]; int g_off[3]; int kc_[3]; bool rowok[3];
#pragma unroll
    for (int j = 0; j < 3; j++) {
        int s4 = tid + 256 * j;
        int kc = s4 / 96;
        int r  = (s4 / 32) % 3;
        int s  = s4 & 31;
        int gh = h - 1 + r;
        kc_[j]    = kc;
        rowok[j]  = (gh >= 0 && gh < 128);
        sm_off[j] = (kc * 3 + r) * ROWSTR + 4 + s * 4;
        g_off[j]  = kc * HW + (rowok[j] ? gh : 0) * 128 + s * 4;
    }

    float C[2][NT][4];
#pragma unroll
    for (int mt = 0; mt < 2; mt++)
#pragma unroll
        for (int nt = 0; nt < NT; nt++)
#pragma unroll
            for (int k = 0; k < 4; k++) C[mt][nt][k] = 0.f;

    auto issue = [&](int chunk) {
        float* buf = s_in + (chunk & 1) * INBUF;
#pragma unroll
        for (int j = 0; j < 3; j++) {
            bool ok = (chunk * 8 + kc_[j] < CIN) && rowok[j];
            const float* src = inN + (ok ? ((size_t)chunk * 8 * HW + g_off[j]) : 0);
            cp16((unsigned)__cvta_generic_to_shared(buf + sm_off[j]), src, ok ? 16 : 0);
        }
        asm volatile("cp.async.commit_group;" ::: "memory");
    };

    issue(0);

    for (int chunk = 0; chunk < CHUNKS; chunk++) {
        asm volatile("cp.async.wait_group 0;" ::: "memory");
        __syncthreads();
        // all warps done reading the other buffer (previous iteration) -> safe
        if (chunk + 1 < CHUNKS) issue(chunk + 1);

        const float* buf = s_in + (chunk & 1) * INBUF;
        const float* wc = mw + (((size_t)chunk * 9) * CO_PAD + cob0 + col + r4h) * 8 + r4 * 2;

#pragma unroll
        for (int dh = 0; dh < 3; dh++) {
#pragma unroll
            for (int dw = 0; dw < 3; dw++) {
                const int tap = dh * 3 + dw;
                float a[2][4];
                {
                    const float* base = buf + r4 * (3 * ROWSTR) + dh * ROWSTR
                                      + pxb + dw + 3 + r4h;
#pragma unroll
                    for (int mt = 0; mt < 2; mt++) {
                        a[mt][0] = base[mt * 16];
                        a[mt][1] = base[mt * 16 + 8];
                        a[mt][2] = base[4 * (3 * ROWSTR) + mt * 16];
                        a[mt][3] = base[4 * (3 * ROWSTR) + mt * 16 + 8];
                    }
                }
#pragma unroll
                for (int nt = 0; nt < NT; nt++) {
                    float2 b = __ldg((const float2*)(wc + ((size_t)tap * CO_PAD + nt * 8) * 8));
#pragma unroll
                    for (int mt = 0; mt < 2; mt++)
                        mma_tf32(C[mt][nt], a[mt], b);
                }
            }
        }
    }

    // ---- epilogue: c0 (px, co) c1 (px, co+1) c2 (px+8, co) c3 (px+8, co+1)
#pragma unroll
    for (int mt = 0; mt < 2; mt++) {
#pragma unroll
        for (int nt = 0; nt < NT; nt++) {
            int px = pxb + mt * 16 + r4h;
            int co = cob0 + col + nt * 8 + r4 * 2;
            size_t o0 = (size_t)h * 128 + px;
#pragma unroll
            for (int half = 0; half < 2; half++) {
                if (co + half < COUT) {
                    float b = bias[co + half];
                    float* op = out + ((size_t)n * COUT + co + half) * HW;
                    float v0 = apply_act(C[mt][nt][half] + b, ACT);
                    float v1 = apply_act(C[mt][nt][2 + half] + b, ACT);
                    if (RND) { v0 = to_tf32(v0); v1 = to_tf32(v1); }
                    op[o0]     = v0;
                    op[o0 + 8] = v1;
                }
            }
        }
    }
}

// ---------------------------------------------------------------------------
// Vector quantizer (groups of 8 along W, torch .view semantics).
// q is stored tf32-rounded for the downstream conv; the loss uses exact emb.
// ---------------------------------------------------------------------------
__global__ __launch_bounds__(256)
void vq_kernel(const float* __restrict__ z, const float* __restrict__ emb,
               float* __restrict__ q, double* __restrict__ part) {
    __shared__ float  s_e[512 * 8];
    __shared__ float  s_hn[512];
    __shared__ double s_red[256];

    const int tid = threadIdx.x;
    for (int i = tid; i < 4096; i += 256) s_e[i] = emb[i];
    __syncthreads();
    for (int k = tid; k < 512; k += 256) {
        float s = 0.f;
#pragma unroll
        for (int j = 0; j < 8; j++) { float e = s_e[k * 8 + j]; s += e * e; }
        s_hn[k] = 0.5f * s;
    }
    __syncthreads();

    const int base = blockIdx.x * 1024 + tid;
    float v[4][8];
#pragma unroll
    for (int u = 0; u < 4; u++) {
        int vi = base + u * 256;
        float4 a = ((const float4*)z)[vi * 2];
        float4 b = ((const float4*)z)[vi * 2 + 1];
        v[u][0] = a.x; v[u][1] = a.y; v[u][2] = a.z; v[u][3] = a.w;
        v[u][4] = b.x; v[u][5] = b.y; v[u][6] = b.z; v[u][7] = b.w;
    }

    float best[4] = {3.4e38f, 3.4e38f, 3.4e38f, 3.4e38f};
    int   bk[4]   = {0, 0, 0, 0};
    for (int k = 0; k < 512; k++) {
        float e0 = s_e[k * 8 + 0], e1 = s_e[k * 8 + 1], e2 = s_e[k * 8 + 2], e3 = s_e[k * 8 + 3];
        float e4 = s_e[k * 8 + 4], e5 = s_e[k * 8 + 5], e6 = s_e[k * 8 + 6], e7 = s_e[k * 8 + 7];
        float hn = s_hn[k];
#pragma unroll
        for (int u = 0; u < 4; u++) {
            float dot = e0 * v[u][0] + e1 * v[u][1] + e2 * v[u][2] + e3 * v[u][3]
                      + e4 * v[u][4] + e5 * v[u][5] + e6 * v[u][6] + e7 * v[u][7];
            float sc = hn - dot;
            if (sc < best[u]) { best[u] = sc; bk[u] = k; }
        }
    }

    float sq = 0.f;
#pragma unroll
    for (int u = 0; u < 4; u++) {
        int vi = base + u * 256;
        int kb = bk[u];
        float4 o1, o2;
        o1.x = to_tf32(s_e[kb * 8 + 0]); o1.y = to_tf32(s_e[kb * 8 + 1]);
        o1.z = to_tf32(s_e[kb * 8 + 2]); o1.w = to_tf32(s_e[kb * 8 + 3]);
        o2.x = to_tf32(s_e[kb * 8 + 4]); o2.y = to_tf32(s_e[kb * 8 + 5]);
        o2.z = to_tf32(s_e[kb * 8 + 6]); o2.w = to_tf32(s_e[kb * 8 + 7]);
#pragma unroll
        for (int j = 0; j < 8; j++) {
            float d = s_e[kb * 8 + j] - v[u][j];   // exact values for the loss
            sq += d * d;
        }
        ((float4*)q)[vi * 2]     = o1;
        ((float4*)q)[vi * 2 + 1] = o2;
    }

    s_red[tid] = (double)sq;
    __syncthreads();
    for (int o = 128; o > 0; o >>= 1) {
        if (tid < o) s_red[tid] += s_red[tid + o];
        __syncthreads();
    }
    if (tid == 0) part[blockIdx.x] = s_red[0];
}

__global__ void finalize_loss(const double* __restrict__ part, float* __restrict__ outp) {
    __shared__ double s[256];
    int tid = threadIdx.x;
    s[tid] = part[tid];
    __syncthreads();
    for (int o = 128; o > 0; o >>= 1) {
        if (tid < o) s[tid] += s[tid + o];
        __syncthreads();
    }
    if (tid == 0) *outp = (float)(1.25 * s[0] / 2097152.0);
}

// ---------------------------------------------------------------------------
extern "C" void kernel_launch(void* const* d_in, const int* in_sizes, int n_in,
                              void* d_out, int out_size) {
    (void)in_sizes; (void)n_in;
    const float* x   = (const float*)d_in[0];
    const float* e1w = (const float*)d_in[1];
    const float* e1b = (const float*)d_in[2];
    const float* e2w = (const float*)d_in[3];
    const float* e2b = (const float*)d_in[4];
    const float* e3w = (const float*)d_in[5];
    const float* e3b = (const float*)d_in[6];
    const float* emb = (const float*)d_in[7];
    const float* d1w = (const float*)d_in[8];
    const float* d1b = (const float*)d_in[9];
    const float* d2w = (const float*)d_in[10];
    const float* d2b = (const float*)d_in[11];
    const float* d3w = (const float*)d_in[12];
    const float* d3b = (const float*)d_in[13];
    float* out = (float*)d_out;

    void *xr, *z1, *z2, *z3, *q, *y1, *y2, *part;
    void *me1, *me2, *me3, *md1, *md2, *md3;
    cudaGetSymbolAddress(&xr,  g_xr);
    cudaGetSymbolAddress(&z1,  g_z1);
    cudaGetSymbolAddress(&z2,  g_z2);
    cudaGetSymbolAddress(&z3,  g_z3);
    cudaGetSymbolAddress(&q,   g_q);
    cudaGetSymbolAddress(&y1,  g_y1);
    cudaGetSymbolAddress(&y2,  g_y2);
    cudaGetSymbolAddress(&me1, g_mw_e1);
    cudaGetSymbolAddress(&me2, g_mw_e2);
    cudaGetSymbolAddress(&me3, g_mw_e3);
    cudaGetSymbolAddress(&md1, g_mw_d1);
    cudaGetSymbolAddress(&md2, g_mw_d2);
    cudaGetSymbolAddress(&md3, g_mw_d3);
    cudaGetSymbolAddress(&part, g_part);

    // ---- weight packing + x rounding
    pack_all<<<(529920 + 255) / 256, 256>>>(
        e1w, e2w, e3w, d1w, d2w, d3w,
        (float*)me1, (float*)me2, (float*)me3,
        (float*)md1, (float*)md2, (float*)md3);
    const int N4 = BATCH * 156 * HW / 4;   // 10,223,616
    round_copy<<<(N4 + 255) / 256, 256>>>(x, (float*)xr, N4);

    // encoder (tf32 tensor path; intermediates stored rounded)
    convmma<156, 128, 64, 1, 0, 128, true ><<<dim3(128, 2, 16), 256>>>((float*)xr, (float*)me1, e1b, (float*)z1);
    convmma<128,  64, 64, 1, 0,  64, true ><<<dim3(128, 1, 16), 256>>>((float*)z1, (float*)me2, e2b, (float*)z2);
    convmma< 64,   8, 16, 1, 0,  16, false><<<dim3(128, 1, 16), 256>>>((float*)z2, (float*)me3, e3b, (float*)z3);

    // vector quantizer + loss partials (exact fp32; q stored rounded)
    vq_kernel<<<256, 256>>>((const float*)z3, emb, (float*)q, (double*)part);

    // decoder (tf32 tensor path)
    convmma<  8,  64, 64, 1, 0,   64, true ><<<dim3(128, 1, 16), 256>>>((float*)q,  (float*)md1, d1b, (float*)y1);
    convmma< 64, 128, 64, 1, 0,  128, true ><<<dim3(128, 2, 16), 256>>>((float*)y1, (float*)md2, d2b, (float*)y2);
    convmma<128, 156, 64, 2, 0,  160, false><<<dim3(128, 2, 16), 256>>>((float*)y2, (float*)md3, d3b, out);
    convmma<128, 156, 32, 2, 128,160, false><<<dim3(128, 1, 16), 256>>>((float*)y2, (float*)md3, d3b, out);

    finalize_loss<<<1, 256>>>((const double*)part, out + (out_size - 1));
}

// round 12
// speedup vs baseline: 2.2287x; 2.2287x over previous
#include <cuda_runtime.h>
#include <cuda_fp16.h>
#include <math.h>

// ---------------------------------------------------------------------------
// VQ-VAE forward.  B=16, L=156, P=8, H=W=128, codebook 512x8.
// R12: fp16 mma.sync m16n8k16 (2x MACs/instr vs tf32 k8, same 10-bit
//      mantissa).  Activations stored as channel-pair-interleaved half2
//      planes; weights packed to B-fragment layout; R10 register-prefetch
//      double-buffer staging (cp.async rejected twice).
// ---------------------------------------------------------------------------

#define BATCH 16
#define HW    16384   // 128*128

__device__ __forceinline__ void mma_f16(float c[4], const unsigned a[4], uint2 b) {
    asm volatile("mma.sync.aligned.m16n8k16.row.col.f32.f16.f16.f32 "
        "{%0,%1,%2,%3}, {%4,%5,%6,%7}, {%8,%9}, {%0,%1,%2,%3};"
        : "+f"(c[0]), "+f"(c[1]), "+f"(c[2]), "+f"(c[3])
        : "r"(a[0]), "r"(a[1]), "r"(a[2]), "r"(a[3]), "r"(b.x), "r"(b.y));
}
__device__ __forceinline__ unsigned h2u(float lo, float hi) {
    __half2 h = __floats2half2_rn(lo, hi);
    return *(unsigned*)&h;
}

// Static device scratch (allocation-free rule).  Activations = half2 planes:
// plane p holds channels (2p, 2p+1) interleaved, [n][p][h][w].
__device__ unsigned g_x16[BATCH * 78 * HW];
__device__ unsigned g_z1h[BATCH * 64 * HW];
__device__ unsigned g_z2h[BATCH * 32 * HW];
__device__ float    g_z3 [BATCH *  8 * HW];     // fp32 for VQ
__device__ unsigned g_qh [BATCH *  4 * HW];
__device__ unsigned g_y1h[BATCH * 32 * HW];
__device__ unsigned g_y2h[BATCH * 64 * HW];
// fp16 weights: [chunk16][tap 9][CO_PAD][slot 8]; slot s -> pair p =
// (s&1)?(s>>1)+4:(s>>1); u32 = half2(w[ci=2p], w[ci=2p+1]).
__device__ unsigned g_w_e1[10 * 9 * 128 * 8];
__device__ unsigned g_w_e2[ 8 * 9 *  64 * 8];
__device__ unsigned g_w_e3[ 4 * 9 *  16 * 8];
__device__ unsigned g_w_d1[ 1 * 9 *  64 * 8];
__device__ unsigned g_w_d2[ 4 * 9 * 128 * 8];
__device__ unsigned g_w_d3[ 8 * 9 * 160 * 8];
__device__ double   g_part[256];

// ---------------------------------------------------------------------------
__device__ void pack16(const float* __restrict__ w, unsigned* __restrict__ out,
                       int CIN, int COUT, int CO_PAD, int transposed, int idx) {
    int s     = idx & 7;
    int co    = (idx >> 3) % CO_PAD;
    int tap   = ((idx >> 3) / CO_PAD) % 9;
    int chunk = ((idx >> 3) / CO_PAD) / 9;
    int p     = (s & 1) ? (s >> 1) + 4 : (s >> 1);
    int ci0   = chunk * 16 + 2 * p, ci1 = ci0 + 1;
    float v0 = 0.f, v1 = 0.f;
    if (co < COUT) {
        if (transposed) {
            if (ci0 < CIN) v0 = w[((size_t)ci0 * COUT + co) * 9 + (8 - tap)];
            if (ci1 < CIN) v1 = w[((size_t)ci1 * COUT + co) * 9 + (8 - tap)];
        } else {
            if (ci0 < CIN) v0 = w[((size_t)co * CIN + ci0) * 9 + tap];
            if (ci1 < CIN) v1 = w[((size_t)co * CIN + ci1) * 9 + tap];
        }
    }
    out[idx] = h2u(v0, v1);
}

__global__ void pack_all(const float* e1w, const float* e2w, const float* e3w,
                         const float* d1w, const float* d2w, const float* d3w,
                         unsigned* we1, unsigned* we2, unsigned* we3,
                         unsigned* wd1, unsigned* wd2, unsigned* wd3) {
    int idx = blockIdx.x * 256 + threadIdx.x;
    if (idx < 92160) { pack16(e1w, we1, 156, 128, 128, 0, idx); return; }
    idx -= 92160;
    if (idx < 36864) { pack16(e2w, we2, 128,  64,  64, 0, idx); return; }
    idx -= 36864;
    if (idx < 4608)  { pack16(e3w, we3,  64,   8,  16, 0, idx); return; }
    idx -= 4608;
    if (idx < 4608)  { pack16(d1w, wd1,   8,  64,  64, 1, idx); return; }
    idx -= 4608;
    if (idx < 36864) { pack16(d2w, wd2,  64, 128, 128, 1, idx); return; }
    idx -= 36864;
    if (idx < 92160) { pack16(d3w, wd3, 128, 156, 160, 1, idx); }
}

// x (fp32 NCHW, 156 ch) -> 78 interleaved half2 planes
__global__ void x_to_h2(const float* __restrict__ x, unsigned* __restrict__ x16) {
    int i = blockIdx.x * 256 + threadIdx.x;
    const int total = BATCH * 78 * (HW / 4);
    if (i >= total) return;
    int hw4 = i % (HW / 4);
    int p   = (i / (HW / 4)) % 78;
    int n   = i / (HW / 4) / 78;
    const float4 a = *(const float4*)(x + ((size_t)n * 156 + 2 * p) * HW + hw4 * 4);
    const float4 b = *(const float4*)(x + ((size_t)n * 156 + 2 * p + 1) * HW + hw4 * 4);
    uint4 o;
    o.x = h2u(a.x, b.x); o.y = h2u(a.y, b.y);
    o.z = h2u(a.z, b.z); o.w = h2u(a.w, b.w);
    ((uint4*)x16)[((size_t)n * 78 + p) * (HW / 4) + hw4] = o;
}

__device__ __forceinline__ float apply_act(float v, int ACT) {
    if (ACT == 1) return fmaxf(v, 0.f);
    if (ACT == 2) return 1.f / (1.f + __expf(-v));
    return v;
}

// ---------------------------------------------------------------------------
// fp16 tensor-core 3x3 same-conv (mma.sync m16n8k16).  Block = (n, row h,
// MT co at CO_OFF).  8 warps: wm=warp&3 -> 32-px span, wn=warp>>2 -> MT/2 co.
// Chunk = 16 input channels = 8 half2 pair-planes.  Smem pair-plane stride
// 440 words -> bank-disjoint A fragments.  B fragments via __ldg (LDG.64,
// coalesced 256B/warp/fragment-row).  Register-prefetch double buffer,
// one __syncthreads per chunk.
// ---------------------------------------------------------------------------
template<int CIN, int COUT, int MT, int ACT, int CO_OFF, int CO_PAD, bool OUTF16>
__global__ __launch_bounds__(256, 3)
void convmma16(const unsigned* __restrict__ in, const unsigned* __restrict__ mw,
               const float* __restrict__ bias, void* __restrict__ outp) {
    constexpr int CINP   = (CIN + 1) / 2;
    constexpr int CHUNKS = (CIN + 15) / 16;
    constexpr int RSTR   = 144;             // words per row (8 halo + 128 + pad)
    constexpr int PSTR   = 440;             // words per pair-plane (3*144 + 8 pad)
    constexpr int BUF    = 8 * PSTR;        // 3520 words per buffer
    constexpr int NT     = MT / 16;

    __shared__ unsigned s_in[2 * BUF];

    const int n    = blockIdx.z;
    const int h    = blockIdx.x;
    const int cob0 = CO_OFF + blockIdx.y * MT;
    const int tid  = threadIdx.x;
    const int lane = tid & 31;
    const int warp = tid >> 5;
    const int wm   = warp & 3;
    const int wn   = warp >> 2;
    const int r4   = lane & 3;
    const int r4h  = lane >> 2;
    const int pxb  = wm * 32;
    const int col  = wn * (MT / 2);

    const unsigned* inN = in + (size_t)n * CINP * HW;

    // zero halo words (7 and 136 of every row, both buffers) once
    if (tid < 96) {
        int w  = tid & 1;
        int r  = (tid >> 1) % 3;
        int pp = ((tid >> 1) / 3) & 7;
        int b  = tid / 48;
        s_in[b * BUF + pp * PSTR + r * RSTR + (w ? 136 : 7)] = 0u;
    }

    // staging slots: s4 = tid + 256*j -> (pair-plane, row, 4-px group)
    int sm_off[3], g_off[3], pp_[3]; bool rowok[3];
#pragma unroll
    for (int j = 0; j < 3; j++) {
        int s4 = tid + 256 * j;
        int pp = s4 / 96, r = (s4 / 32) % 3, s = s4 & 31;
        int gh = h - 1 + r;
        pp_[j]    = pp;
        rowok[j]  = (gh >= 0 && gh < 128);
        sm_off[j] = pp * PSTR + r * RSTR + 8 + 4 * s;
        g_off[j]  = pp * HW + (rowok[j] ? gh : 0) * 128 + 4 * s;
    }

    float C[2][NT][4];
#pragma unroll
    for (int mt = 0; mt < 2; mt++)
#pragma unroll
        for (int nt = 0; nt < NT; nt++)
#pragma unroll
            for (int k = 0; k < 4; k++) C[mt][nt][k] = 0.f;

    uint4 pf[3];
#pragma unroll
    for (int j = 0; j < 3; j++) {
        bool ok = (pp_[j] < CINP) && rowok[j];
        pf[j] = ok ? *(const uint4*)(inN + g_off[j]) : make_uint4(0, 0, 0, 0);
    }

    for (int chunk = 0; chunk < CHUNKS; chunk++) {
        unsigned* buf = s_in + (chunk & 1) * BUF;
#pragma unroll
        for (int j = 0; j < 3; j++) *(uint4*)(buf + sm_off[j]) = pf[j];
        __syncthreads();

        if (chunk + 1 < CHUNKS) {
#pragma unroll
            for (int j = 0; j < 3; j++) {
                bool ok = ((chunk + 1) * 8 + pp_[j] < CINP) && rowok[j];
                pf[j] = ok ? *(const uint4*)(inN + (size_t)(chunk + 1) * 8 * HW + g_off[j])
                           : make_uint4(0, 0, 0, 0);
            }
        }

        const unsigned* wc = mw + (((size_t)chunk * 9) * CO_PAD + cob0 + col + r4h) * 8 + r4 * 2;

#pragma unroll
        for (int dh = 0; dh < 3; dh++) {
#pragma unroll
            for (int dw = 0; dw < 3; dw++) {
                const int tap = dh * 3 + dw;
                const unsigned* base = buf + dh * RSTR + 7 + dw + pxb + r4h;
                unsigned a[2][4];
#pragma unroll
                for (int mt = 0; mt < 2; mt++) {
                    a[mt][0] = base[r4 * PSTR + mt * 16];
                    a[mt][1] = base[r4 * PSTR + mt * 16 + 8];
                    a[mt][2] = base[(r4 + 4) * PSTR + mt * 16];
                    a[mt][3] = base[(r4 + 4) * PSTR + mt * 16 + 8];
                }
#pragma unroll
                for (int nt = 0; nt < NT; nt++) {
                    uint2 b = __ldg((const uint2*)(wc + ((size_t)tap * CO_PAD + nt * 8) * 8));
                    mma_f16(C[0][nt], a[0], b);
                    mma_f16(C[1][nt], a[1], b);
                }
            }
        }
    }

    // epilogue: c0 (px, co) c1 (px, co+1) c2 (px+8, co) c3 (px+8, co+1),
    // co = cob0 + col + nt*8 + 2*r4
#pragma unroll
    for (int mt = 0; mt < 2; mt++) {
#pragma unroll
        for (int nt = 0; nt < NT; nt++) {
            int px = pxb + mt * 16 + r4h;
            int co = cob0 + col + nt * 8 + 2 * r4;
            if (OUTF16) {
                float b0 = bias[co], b1 = bias[co + 1];
                unsigned* op = (unsigned*)outp
                    + ((size_t)n * (COUT / 2) + (co >> 1)) * HW + h * 128 + px;
                op[0] = h2u(apply_act(C[mt][nt][0] + b0, ACT),
                            apply_act(C[mt][nt][1] + b1, ACT));
                op[8] = h2u(apply_act(C[mt][nt][2] + b0, ACT),
                            apply_act(C[mt][nt][3] + b1, ACT));
            } else {
#pragma unroll
                for (int half = 0; half < 2; half++) {
                    if (co + half < COUT) {
                        float b = bias[co + half];
                        float* op = (float*)outp + ((size_t)n * COUT + co + half) * HW
                                  + h * 128 + px;
                        op[0] = apply_act(C[mt][nt][half] + b, ACT);
                        op[8] = apply_act(C[mt][nt][2 + half] + b, ACT);
                    }
                }
            }
        }
    }
}

// ---------------------------------------------------------------------------
// Vector quantizer.  Vectors = 8 consecutive W pixels of one channel (torch
// .view semantics).  Re-parallelized over channel PAIRS so q is written
// directly as interleaved half2 planes for the fp16 decoder.  Loss exact fp32.
// ---------------------------------------------------------------------------
__global__ __launch_bounds__(256)
void vq_kernel(const float* __restrict__ z, const float* __restrict__ emb,
               unsigned* __restrict__ q16, double* __restrict__ part) {
    __shared__ float  s_e[512 * 8];
    __shared__ float  s_hn[512];
    __shared__ double s_red[256];

    const int tid = threadIdx.x;
    for (int i = tid; i < 4096; i += 256) s_e[i] = emb[i];
    __syncthreads();
    for (int k = tid; k < 512; k += 256) {
        float s = 0.f;
#pragma unroll
        for (int j = 0; j < 8; j++) { float e = s_e[k * 8 + j]; s += e * e; }
        s_hn[k] = 0.5f * s;
    }
    __syncthreads();

    // 2 channel-pairs per thread; pair pi -> vectors (c=2c2) and (c=2c2+1)
    const int pbase = blockIdx.x * 512 + tid;
    float v[4][8];
    int vi0s[2];
#pragma unroll
    for (int u = 0; u < 2; u++) {
        int pi = pbase + 256 * u;
        int wg = pi & 15, hh = (pi >> 4) & 127, c2 = (pi >> 11) & 3, nn = pi >> 13;
        int vi0 = ((nn * 8 + 2 * c2) * 128 + hh) * 16 + wg;
        vi0s[u] = vi0;
#pragma unroll
        for (int e = 0; e < 2; e++) {
            int vi = vi0 + e * 2048;
            float4 a = ((const float4*)z)[vi * 2];
            float4 b = ((const float4*)z)[vi * 2 + 1];
            float* vv = v[2 * u + e];
            vv[0] = a.x; vv[1] = a.y; vv[2] = a.z; vv[3] = a.w;
            vv[4] = b.x; vv[5] = b.y; vv[6] = b.z; vv[7] = b.w;
        }
    }

    float best[4] = {3.4e38f, 3.4e38f, 3.4e38f, 3.4e38f};
    int   bk[4]   = {0, 0, 0, 0};
    for (int k = 0; k < 512; k++) {
        float e0 = s_e[k * 8 + 0], e1 = s_e[k * 8 + 1], e2 = s_e[k * 8 + 2], e3 = s_e[k * 8 + 3];
        float e4 = s_e[k * 8 + 4], e5 = s_e[k * 8 + 5], e6 = s_e[k * 8 + 6], e7 = s_e[k * 8 + 7];
        float hn = s_hn[k];
#pragma unroll
        for (int u = 0; u < 4; u++) {
            float dot = e0 * v[u][0] + e1 * v[u][1] + e2 * v[u][2] + e3 * v[u][3]
                      + e4 * v[u][4] + e5 * v[u][5] + e6 * v[u][6] + e7 * v[u][7];
            float sc = hn - dot;
            if (sc < best[u]) { best[u] = sc; bk[u] = k; }
        }
    }

    float sq = 0.f;
#pragma unroll
    for (int u = 0; u < 2; u++) {
        int pi = pbase + 256 * u;
        int wg = pi & 15, hh = (pi >> 4) & 127, c2 = (pi >> 11) & 3, nn = pi >> 13;
        int k0 = bk[2 * u], k1 = bk[2 * u + 1];
        unsigned o[8];
#pragma unroll
        for (int j = 0; j < 8; j++) {
            o[j] = h2u(s_e[k0 * 8 + j], s_e[k1 * 8 + j]);
            float d0 = s_e[k0 * 8 + j] - v[2 * u][j];
            float d1 = s_e[k1 * 8 + j] - v[2 * u + 1][j];
            sq += d0 * d0 + d1 * d1;
        }
        size_t dst = ((size_t)(nn * 4 + c2)) * HW + hh * 128 + wg * 8;
        ((uint4*)q16)[dst / 4]     = make_uint4(o[0], o[1], o[2], o[3]);
        ((uint4*)q16)[dst / 4 + 1] = make_uint4(o[4], o[5], o[6], o[7]);
        (void)vi0s;
    }

    s_red[tid] = (double)sq;
    __syncthreads();
    for (int o = 128; o > 0; o >>= 1) {
        if (tid < o) s_red[tid] += s_red[tid + o];
        __syncthreads();
    }
    if (tid == 0) part[blockIdx.x] = s_red[0];
}

__global__ void finalize_loss(const double* __restrict__ part, float* __restrict__ outp) {
    __shared__ double s[256];
    int tid = threadIdx.x;
    s[tid] = part[tid];
    __syncthreads();
    for (int o = 128; o > 0; o >>= 1) {
        if (tid < o) s[tid] += s[tid + o];
        __syncthreads();
    }
    if (tid == 0) *outp = (float)(1.25 * s[0] / 2097152.0);
}

// ---------------------------------------------------------------------------
extern "C" void kernel_launch(void* const* d_in, const int* in_sizes, int n_in,
                              void* d_out, int out_size) {
    (void)in_sizes; (void)n_in;
    const float* x   = (const float*)d_in[0];
    const float* e1w = (const float*)d_in[1];
    const float* e1b = (const float*)d_in[2];
    const float* e2w = (const float*)d_in[3];
    const float* e2b = (const float*)d_in[4];
    const float* e3w = (const float*)d_in[5];
    const float* e3b = (const float*)d_in[6];
    const float* emb = (const float*)d_in[7];
    const float* d1w = (const float*)d_in[8];
    const float* d1b = (const float*)d_in[9];
    const float* d2w = (const float*)d_in[10];
    const float* d2b = (const float*)d_in[11];
    const float* d3w = (const float*)d_in[12];
    const float* d3b = (const float*)d_in[13];
    float* out = (float*)d_out;

    void *x16, *z1h, *z2h, *z3, *qh, *y1h, *y2h, *part;
    void *we1, *we2, *we3, *wd1, *wd2, *wd3;
    cudaGetSymbolAddress(&x16, g_x16);
    cudaGetSymbolAddress(&z1h, g_z1h);
    cudaGetSymbolAddress(&z2h, g_z2h);
    cudaGetSymbolAddress(&z3,  g_z3);
    cudaGetSymbolAddress(&qh,  g_qh);
    cudaGetSymbolAddress(&y1h, g_y1h);
    cudaGetSymbolAddress(&y2h, g_y2h);
    cudaGetSymbolAddress(&we1, g_w_e1);
    cudaGetSymbolAddress(&we2, g_w_e2);
    cudaGetSymbolAddress(&we3, g_w_e3);
    cudaGetSymbolAddress(&wd1, g_w_d1);
    cudaGetSymbolAddress(&wd2, g_w_d2);
    cudaGetSymbolAddress(&wd3, g_w_d3);
    cudaGetSymbolAddress(&part, g_part);

    // ---- weight packing (267264 items) + x conversion
    pack_all<<<(267264 + 255) / 256, 256>>>(
        e1w, e2w, e3w, d1w, d2w, d3w,
        (unsigned*)we1, (unsigned*)we2, (unsigned*)we3,
        (unsigned*)wd1, (unsigned*)wd2, (unsigned*)wd3);
    const int NX = BATCH * 78 * (HW / 4);
    x_to_h2<<<(NX + 255) / 256, 256>>>(x, (unsigned*)x16);

    // encoder (fp16 tensor path)
    convmma16<156, 128, 64, 1, 0, 128, true >
        <<<dim3(128, 2, 16), 256>>>((unsigned*)x16, (unsigned*)we1, e1b, z1h);
    convmma16<128,  64, 64, 1, 0,  64, true >
        <<<dim3(128, 1, 16), 256>>>((unsigned*)z1h, (unsigned*)we2, e2b, z2h);
    convmma16< 64,   8, 16, 1, 0,  16, false>
        <<<dim3(128, 1, 16), 256>>>((unsigned*)z2h, (unsigned*)we3, e3b, z3);

    // vector quantizer + loss partials (exact fp32; q emitted as half2 pairs)
    vq_kernel<<<256, 256>>>((const float*)z3, emb, (unsigned*)qh, (double*)part);

    // decoder (fp16 tensor path)
    convmma16<  8,  64, 64, 1, 0,  64, true >
        <<<dim3(128, 1, 16), 256>>>((unsigned*)qh,  (unsigned*)wd1, d1b, y1h);
    convmma16< 64, 128, 64, 1, 0, 128, true >
        <<<dim3(128, 2, 16), 256>>>((unsigned*)y1h, (unsigned*)wd2, d2b, y2h);
    convmma16<128, 156, 64, 2, 0, 160, false>
        <<<dim3(128, 2, 16), 256>>>((unsigned*)y2h, (unsigned*)wd3, d3b, out);
    convmma16<128, 156, 32, 2, 128, 160, false>
        <<<dim3(128, 1, 16), 256>>>((unsigned*)y2h, (unsigned*)wd3, d3b, out);

    finalize_loss<<<1, 256>>>((const double*)part, out + (out_size - 1));
}

// round 13
// speedup vs baseline: 2.6132x; 1.1725x over previous
#include <cuda_runtime.h>
#include <cuda_fp16.h>
#include <math.h>

// ---------------------------------------------------------------------------
// VQ-VAE forward.  B=16, L=156, P=8, H=W=128, codebook 512x8.
// R13: staging-amortization round on top of R12 fp16 k16:
//      - e1/d2 at MT=128 (NT=8): 3.3 issues/MMA vs 5.2, barriers/MMA halved
//      - d3 single MT=80 (NT=5) launch (kills the re-staging MT=32 tail)
//      Accumulation order untouched -> bit-identical numerics to R12.
// ---------------------------------------------------------------------------

#define BATCH 16
#define HW    16384   // 128*128

__device__ __forceinline__ void mma_f16(float c[4], const unsigned a[4], uint2 b) {
    asm volatile("mma.sync.aligned.m16n8k16.row.col.f32.f16.f16.f32 "
        "{%0,%1,%2,%3}, {%4,%5,%6,%7}, {%8,%9}, {%0,%1,%2,%3};"
        : "+f"(c[0]), "+f"(c[1]), "+f"(c[2]), "+f"(c[3])
        : "r"(a[0]), "r"(a[1]), "r"(a[2]), "r"(a[3]), "r"(b.x), "r"(b.y));
}
__device__ __forceinline__ unsigned h2u(float lo, float hi) {
    __half2 h = __floats2half2_rn(lo, hi);
    return *(unsigned*)&h;
}

// Static device scratch (allocation-free rule).  Activations = half2 planes:
// plane p holds channels (2p, 2p+1) interleaved, [n][p][h][w].
__device__ unsigned g_x16[BATCH * 78 * HW];
__device__ unsigned g_z1h[BATCH * 64 * HW];
__device__ unsigned g_z2h[BATCH * 32 * HW];
__device__ float    g_z3 [BATCH *  8 * HW];     // fp32 for VQ
__device__ unsigned g_qh [BATCH *  4 * HW];
__device__ unsigned g_y1h[BATCH * 32 * HW];
__device__ unsigned g_y2h[BATCH * 64 * HW];
// fp16 weights: [chunk16][tap 9][CO_PAD][slot 8]; slot s -> pair p =
// (s&1)?(s>>1)+4:(s>>1); u32 = half2(w[ci=2p], w[ci=2p+1]).
__device__ unsigned g_w_e1[10 * 9 * 128 * 8];
__device__ unsigned g_w_e2[ 8 * 9 *  64 * 8];
__device__ unsigned g_w_e3[ 4 * 9 *  16 * 8];
__device__ unsigned g_w_d1[ 1 * 9 *  64 * 8];
__device__ unsigned g_w_d2[ 4 * 9 * 128 * 8];
__device__ unsigned g_w_d3[ 8 * 9 * 160 * 8];
__device__ double   g_part[256];

// ---------------------------------------------------------------------------
__device__ void pack16(const float* __restrict__ w, unsigned* __restrict__ out,
                       int CIN, int COUT, int CO_PAD, int transposed, int idx) {
    int s     = idx & 7;
    int co    = (idx >> 3) % CO_PAD;
    int tap   = ((idx >> 3) / CO_PAD) % 9;
    int chunk = ((idx >> 3) / CO_PAD) / 9;
    int p     = (s & 1) ? (s >> 1) + 4 : (s >> 1);
    int ci0   = chunk * 16 + 2 * p, ci1 = ci0 + 1;
    float v0 = 0.f, v1 = 0.f;
    if (co < COUT) {
        if (transposed) {
            if (ci0 < CIN) v0 = w[((size_t)ci0 * COUT + co) * 9 + (8 - tap)];
            if (ci1 < CIN) v1 = w[((size_t)ci1 * COUT + co) * 9 + (8 - tap)];
        } else {
            if (ci0 < CIN) v0 = w[((size_t)co * CIN + ci0) * 9 + tap];
            if (ci1 < CIN) v1 = w[((size_t)co * CIN + ci1) * 9 + tap];
        }
    }
    out[idx] = h2u(v0, v1);
}

__global__ void pack_all(const float* e1w, const float* e2w, const float* e3w,
                         const float* d1w, const float* d2w, const float* d3w,
                         unsigned* we1, unsigned* we2, unsigned* we3,
                         unsigned* wd1, unsigned* wd2, unsigned* wd3) {
    int idx = blockIdx.x * 256 + threadIdx.x;
    if (idx < 92160) { pack16(e1w, we1, 156, 128, 128, 0, idx); return; }
    idx -= 92160;
    if (idx < 36864) { pack16(e2w, we2, 128,  64,  64, 0, idx); return; }
    idx -= 36864;
    if (idx < 4608)  { pack16(e3w, we3,  64,   8,  16, 0, idx); return; }
    idx -= 4608;
    if (idx < 4608)  { pack16(d1w, wd1,   8,  64,  64, 1, idx); return; }
    idx -= 4608;
    if (idx < 36864) { pack16(d2w, wd2,  64, 128, 128, 1, idx); return; }
    idx -= 36864;
    if (idx < 92160) { pack16(d3w, wd3, 128, 156, 160, 1, idx); }
}

// x (fp32 NCHW, 156 ch) -> 78 interleaved half2 planes
__global__ void x_to_h2(const float* __restrict__ x, unsigned* __restrict__ x16) {
    int i = blockIdx.x * 256 + threadIdx.x;
    const int total = BATCH * 78 * (HW / 4);
    if (i >= total) return;
    int hw4 = i % (HW / 4);
    int p   = (i / (HW / 4)) % 78;
    int n   = i / (HW / 4) / 78;
    const float4 a = *(const float4*)(x + ((size_t)n * 156 + 2 * p) * HW + hw4 * 4);
    const float4 b = *(const float4*)(x + ((size_t)n * 156 + 2 * p + 1) * HW + hw4 * 4);
    uint4 o;
    o.x = h2u(a.x, b.x); o.y = h2u(a.y, b.y);
    o.z = h2u(a.z, b.z); o.w = h2u(a.w, b.w);
    ((uint4*)x16)[((size_t)n * 78 + p) * (HW / 4) + hw4] = o;
}

__device__ __forceinline__ float apply_act(float v, int ACT) {
    if (ACT == 1) return fmaxf(v, 0.f);
    if (ACT == 2) return 1.f / (1.f + __expf(-v));
    return v;
}

// ---------------------------------------------------------------------------
// fp16 tensor-core 3x3 same-conv (mma.sync m16n8k16).  Block = (n, row h,
// MT co at CO_OFF).  8 warps: wm=warp&3 -> 32-px span, wn=warp>>2 -> MT/2 co.
// Chunk = 16 input channels = 8 half2 pair-planes.  Smem pair-plane stride
// 440 words -> bank-disjoint A fragments.  B fragments via __ldg (LDG.64,
// coalesced).  Register-prefetch double buffer, one __syncthreads per chunk.
// ---------------------------------------------------------------------------
template<int CIN, int COUT, int MT, int ACT, int CO_OFF, int CO_PAD, bool OUTF16, int NBLK>
__global__ __launch_bounds__(256, NBLK)
void convmma16(const unsigned* __restrict__ in, const unsigned* __restrict__ mw,
               const float* __restrict__ bias, void* __restrict__ outp) {
    constexpr int CINP   = (CIN + 1) / 2;
    constexpr int CHUNKS = (CIN + 15) / 16;
    constexpr int RSTR   = 144;             // words per row (8 halo + 128 + pad)
    constexpr int PSTR   = 440;             // words per pair-plane (3*144 + 8 pad)
    constexpr int BUF    = 8 * PSTR;        // 3520 words per buffer
    constexpr int NT     = MT / 16;

    __shared__ unsigned s_in[2 * BUF];

    const int n    = blockIdx.z;
    const int h    = blockIdx.x;
    const int cob0 = CO_OFF + blockIdx.y * MT;
    const int tid  = threadIdx.x;
    const int lane = tid & 31;
    const int warp = tid >> 5;
    const int wm   = warp & 3;
    const int wn   = warp >> 2;
    const int r4   = lane & 3;
    const int r4h  = lane >> 2;
    const int pxb  = wm * 32;
    const int col  = wn * (MT / 2);

    const unsigned* inN = in + (size_t)n * CINP * HW;

    // zero halo words (7 and 136 of every row, both buffers) once
    if (tid < 96) {
        int w  = tid & 1;
        int r  = (tid >> 1) % 3;
        int pp = ((tid >> 1) / 3) & 7;
        int b  = tid / 48;
        s_in[b * BUF + pp * PSTR + r * RSTR + (w ? 136 : 7)] = 0u;
    }

    // staging slots: s4 = tid + 256*j -> (pair-plane, row, 4-px group)
    int sm_off[3], g_off[3], pp_[3]; bool rowok[3];
#pragma unroll
    for (int j = 0; j < 3; j++) {
        int s4 = tid + 256 * j;
        int pp = s4 / 96, r = (s4 / 32) % 3, s = s4 & 31;
        int gh = h - 1 + r;
        pp_[j]    = pp;
        rowok[j]  = (gh >= 0 && gh < 128);
        sm_off[j] = pp * PSTR + r * RSTR + 8 + 4 * s;
        g_off[j]  = pp * HW + (rowok[j] ? gh : 0) * 128 + 4 * s;
    }

    float C[2][NT][4];
#pragma unroll
    for (int mt = 0; mt < 2; mt++)
#pragma unroll
        for (int nt = 0; nt < NT; nt++)
#pragma unroll
            for (int k = 0; k < 4; k++) C[mt][nt][k] = 0.f;

    uint4 pf[3];
#pragma unroll
    for (int j = 0; j < 3; j++) {
        bool ok = (pp_[j] < CINP) && rowok[j];
        pf[j] = ok ? *(const uint4*)(inN + g_off[j]) : make_uint4(0, 0, 0, 0);
    }

    for (int chunk = 0; chunk < CHUNKS; chunk++) {
        unsigned* buf = s_in + (chunk & 1) * BUF;
#pragma unroll
        for (int j = 0; j < 3; j++) *(uint4*)(buf + sm_off[j]) = pf[j];
        __syncthreads();

        if (chunk + 1 < CHUNKS) {
#pragma unroll
            for (int j = 0; j < 3; j++) {
                bool ok = ((chunk + 1) * 8 + pp_[j] < CINP) && rowok[j];
                pf[j] = ok ? *(const uint4*)(inN + (size_t)(chunk + 1) * 8 * HW + g_off[j])
                           : make_uint4(0, 0, 0, 0);
            }
        }

        const unsigned* wc = mw + (((size_t)chunk * 9) * CO_PAD + cob0 + col + r4h) * 8 + r4 * 2;

#pragma unroll
        for (int dh = 0; dh < 3; dh++) {
#pragma unroll
            for (int dw = 0; dw < 3; dw++) {
                const int tap = dh * 3 + dw;
                const unsigned* base = buf + dh * RSTR + 7 + dw + pxb + r4h;
                unsigned a[2][4];
#pragma unroll
                for (int mt = 0; mt < 2; mt++) {
                    a[mt][0] = base[r4 * PSTR + mt * 16];
                    a[mt][1] = base[r4 * PSTR + mt * 16 + 8];
                    a[mt][2] = base[(r4 + 4) * PSTR + mt * 16];
                    a[mt][3] = base[(r4 + 4) * PSTR + mt * 16 + 8];
                }
#pragma unroll
                for (int nt = 0; nt < NT; nt++) {
                    uint2 b = __ldg((const uint2*)(wc + ((size_t)tap * CO_PAD + nt * 8) * 8));
                    mma_f16(C[0][nt], a[0], b);
                    mma_f16(C[1][nt], a[1], b);
                }
            }
        }
    }

    // epilogue: c0 (px, co) c1 (px, co+1) c2 (px+8, co) c3 (px+8, co+1),
    // co = cob0 + col + nt*8 + 2*r4
#pragma unroll
    for (int mt = 0; mt < 2; mt++) {
#pragma unroll
        for (int nt = 0; nt < NT; nt++) {
            int px = pxb + mt * 16 + r4h;
            int co = cob0 + col + nt * 8 + 2 * r4;
            if (OUTF16) {
                float b0 = bias[co], b1 = bias[co + 1];
                unsigned* op = (unsigned*)outp
                    + ((size_t)n * (COUT / 2) + (co >> 1)) * HW + h * 128 + px;
                op[0] = h2u(apply_act(C[mt][nt][0] + b0, ACT),
                            apply_act(C[mt][nt][1] + b1, ACT));
                op[8] = h2u(apply_act(C[mt][nt][2] + b0, ACT),
                            apply_act(C[mt][nt][3] + b1, ACT));
            } else {
#pragma unroll
                for (int half = 0; half < 2; half++) {
                    if (co + half < COUT) {
                        float b = bias[co + half];
                        float* op = (float*)outp + ((size_t)n * COUT + co + half) * HW
                                  + h * 128 + px;
                        op[0] = apply_act(C[mt][nt][half] + b, ACT);
                        op[8] = apply_act(C[mt][nt][2 + half] + b, ACT);
                    }
                }
            }
        }
    }
}

// ---------------------------------------------------------------------------
// Vector quantizer.  Vectors = 8 consecutive W pixels of one channel (torch
// .view semantics).  Parallelized over channel PAIRS so q is written directly
// as interleaved half2 planes for the fp16 decoder.  Loss exact fp32.
// ---------------------------------------------------------------------------
__global__ __launch_bounds__(256)
void vq_kernel(const float* __restrict__ z, const float* __restrict__ emb,
               unsigned* __restrict__ q16, double* __restrict__ part) {
    __shared__ float  s_e[512 * 8];
    __shared__ float  s_hn[512];
    __shared__ double s_red[256];

    const int tid = threadIdx.x;
    for (int i = tid; i < 4096; i += 256) s_e[i] = emb[i];
    __syncthreads();
    for (int k = tid; k < 512; k += 256) {
        float s = 0.f;
#pragma unroll
        for (int j = 0; j < 8; j++) { float e = s_e[k * 8 + j]; s += e * e; }
        s_hn[k] = 0.5f * s;
    }
    __syncthreads();

    const int pbase = blockIdx.x * 512 + tid;
    float v[4][8];
#pragma unroll
    for (int u = 0; u < 2; u++) {
        int pi = pbase + 256 * u;
        int wg = pi & 15, hh = (pi >> 4) & 127, c2 = (pi >> 11) & 3, nn = pi >> 13;
        int vi0 = ((nn * 8 + 2 * c2) * 128 + hh) * 16 + wg;
#pragma unroll
        for (int e = 0; e < 2; e++) {
            int vi = vi0 + e * 2048;
            float4 a = ((const float4*)z)[vi * 2];
            float4 b = ((const float4*)z)[vi * 2 + 1];
            float* vv = v[2 * u + e];
            vv[0] = a.x; vv[1] = a.y; vv[2] = a.z; vv[3] = a.w;
            vv[4] = b.x; vv[5] = b.y; vv[6] = b.z; vv[7] = b.w;
        }
    }

    float best[4] = {3.4e38f, 3.4e38f, 3.4e38f, 3.4e38f};
    int   bk[4]   = {0, 0, 0, 0};
    for (int k = 0; k < 512; k++) {
        float e0 = s_e[k * 8 + 0], e1 = s_e[k * 8 + 1], e2 = s_e[k * 8 + 2], e3 = s_e[k * 8 + 3];
        float e4 = s_e[k * 8 + 4], e5 = s_e[k * 8 + 5], e6 = s_e[k * 8 + 6], e7 = s_e[k * 8 + 7];
        float hn = s_hn[k];
#pragma unroll
        for (int u = 0; u < 4; u++) {
            float dot = e0 * v[u][0] + e1 * v[u][1] + e2 * v[u][2] + e3 * v[u][3]
                      + e4 * v[u][4] + e5 * v[u][5] + e6 * v[u][6] + e7 * v[u][7];
            float sc = hn - dot;
            if (sc < best[u]) { best[u] = sc; bk[u] = k; }
        }
    }

    float sq = 0.f;
#pragma unroll
    for (int u = 0; u < 2; u++) {
        int pi = pbase + 256 * u;
        int wg = pi & 15, hh = (pi >> 4) & 127, c2 = (pi >> 11) & 3, nn = pi >> 13;
        int k0 = bk[2 * u], k1 = bk[2 * u + 1];
        unsigned o[8];
#pragma unroll
        for (int j = 0; j < 8; j++) {
            o[j] = h2u(s_e[k0 * 8 + j], s_e[k1 * 8 + j]);
            float d0 = s_e[k0 * 8 + j] - v[2 * u][j];
            float d1 = s_e[k1 * 8 + j] - v[2 * u + 1][j];
            sq += d0 * d0 + d1 * d1;
        }
        size_t dst = ((size_t)(nn * 4 + c2)) * HW + hh * 128 + wg * 8;
        ((uint4*)q16)[dst / 4]     = make_uint4(o[0], o[1], o[2], o[3]);
        ((uint4*)q16)[dst / 4 + 1] = make_uint4(o[4], o[5], o[6], o[7]);
    }

    s_red[tid] = (double)sq;
    __syncthreads();
    for (int o = 128; o > 0; o >>= 1) {
        if (tid < o) s_red[tid] += s_red[tid + o];
        __syncthreads();
    }
    if (tid == 0) part[blockIdx.x] = s_red[0];
}

__global__ void finalize_loss(const double* __restrict__ part, float* __restrict__ outp) {
    __shared__ double s[256];
    int tid = threadIdx.x;
    s[tid] = part[tid];
    __syncthreads();
    for (int o = 128; o > 0; o >>= 1) {
        if (tid < o) s[tid] += s[tid + o];
        __syncthreads();
    }
    if (tid == 0) *outp = (float)(1.25 * s[0] / 2097152.0);
}

// ---------------------------------------------------------------------------
extern "C" void kernel_launch(void* const* d_in, const int* in_sizes, int n_in,
                              void* d_out, int out_size) {
    (void)in_sizes; (void)n_in;
    const float* x   = (const float*)d_in[0];
    const float* e1w = (const float*)d_in[1];
    const float* e1b = (const float*)d_in[2];
    const float* e2w = (const float*)d_in[3];
    const float* e2b = (const float*)d_in[4];
    const float* e3w = (const float*)d_in[5];
    const float* e3b = (const float*)d_in[6];
    const float* emb = (const float*)d_in[7];
    const float* d1w = (const float*)d_in[8];
    const float* d1b = (const float*)d_in[9];
    const float* d2w = (const float*)d_in[10];
    const float* d2b = (const float*)d_in[11];
    const float* d3w = (const float*)d_in[12];
    const float* d3b = (const float*)d_in[13];
    float* out = (float*)d_out;

    void *x16, *z1h, *z2h, *z3, *qh, *y1h, *y2h, *part;
    void *we1, *we2, *we3, *wd1, *wd2, *wd3;
    cudaGetSymbolAddress(&x16, g_x16);
    cudaGetSymbolAddress(&z1h, g_z1h);
    cudaGetSymbolAddress(&z2h, g_z2h);
    cudaGetSymbolAddress(&z3,  g_z3);
    cudaGetSymbolAddress(&qh,  g_qh);
    cudaGetSymbolAddress(&y1h, g_y1h);
    cudaGetSymbolAddress(&y2h, g_y2h);
    cudaGetSymbolAddress(&we1, g_w_e1);
    cudaGetSymbolAddress(&we2, g_w_e2);
    cudaGetSymbolAddress(&we3, g_w_e3);
    cudaGetSymbolAddress(&wd1, g_w_d1);
    cudaGetSymbolAddress(&wd2, g_w_d2);
    cudaGetSymbolAddress(&wd3, g_w_d3);
    cudaGetSymbolAddress(&part, g_part);

    // ---- weight packing (267264 items) + x conversion
    pack_all<<<(267264 + 255) / 256, 256>>>(
        e1w, e2w, e3w, d1w, d2w, d3w,
        (unsigned*)we1, (unsigned*)we2, (unsigned*)we3,
        (unsigned*)wd1, (unsigned*)wd2, (unsigned*)wd3);
    const int NX = BATCH * 78 * (HW / 4);
    x_to_h2<<<(NX + 255) / 256, 256>>>(x, (unsigned*)x16);

    // encoder (fp16 tensor path)
    convmma16<156, 128, 128, 1, 0, 128, true, 2>
        <<<dim3(128, 1, 16), 256>>>((unsigned*)x16, (unsigned*)we1, e1b, z1h);
    convmma16<128,  64,  64, 1, 0,  64, true, 3>
        <<<dim3(128, 1, 16), 256>>>((unsigned*)z1h, (unsigned*)we2, e2b, z2h);
    convmma16< 64,   8,  16, 1, 0,  16, false, 3>
        <<<dim3(128, 1, 16), 256>>>((unsigned*)z2h, (unsigned*)we3, e3b, z3);

    // vector quantizer + loss partials (exact fp32; q emitted as half2 pairs)
    vq_kernel<<<256, 256>>>((const float*)z3, emb, (unsigned*)qh, (double*)part);

    // decoder (fp16 tensor path)
    convmma16<  8,  64,  64, 1, 0,  64, true, 3>
        <<<dim3(128, 1, 16), 256>>>((unsigned*)qh,  (unsigned*)wd1, d1b, y1h);
    convmma16< 64, 128, 128, 1, 0, 128, true, 2>
        <<<dim3(128, 1, 16), 256>>>((unsigned*)y1h, (unsigned*)wd2, d2b, y2h);
    convmma16<128, 156,  80, 2, 0, 160, false, 2>
        <<<dim3(128, 2, 16), 256>>>((unsigned*)y2h, (unsigned*)wd3, d3b, out);

    finalize_loss<<<1, 256>>>((const double*)part, out + (out_size - 1));
}

// round 14
// speedup vs baseline: 2.7904x; 1.0678x over previous
#include <cuda_runtime.h>
#include <cuda_fp16.h>
#include <math.h>

// ---------------------------------------------------------------------------
// VQ-VAE forward.  B=16, L=156, P=8, H=W=128, codebook 512x8.
// R14: NHWC16 fp16 activation layout ([n][chunk16][h][w][16ch]) + ldmatrix.x4
//      A-fragment loads (1 LDSM vs 8 LDS.32 per fragment), pure-copy staging.
//      MMA operand VALUES and accumulation order identical to R13.
// ---------------------------------------------------------------------------

#define BATCH 16
#define HW    16384   // 128*128

__device__ __forceinline__ void mma_f16(float c[4], const unsigned a[4], uint2 b) {
    asm volatile("mma.sync.aligned.m16n8k16.row.col.f32.f16.f16.f32 "
        "{%0,%1,%2,%3}, {%4,%5,%6,%7}, {%8,%9}, {%0,%1,%2,%3};"
        : "+f"(c[0]), "+f"(c[1]), "+f"(c[2]), "+f"(c[3])
        : "r"(a[0]), "r"(a[1]), "r"(a[2]), "r"(a[3]), "r"(b.x), "r"(b.y));
}
__device__ __forceinline__ void ldsm4(unsigned a[4], unsigned addr) {
    asm volatile("ldmatrix.sync.aligned.m8n8.x4.shared.b16 {%0,%1,%2,%3}, [%4];"
        : "=r"(a[0]), "=r"(a[1]), "=r"(a[2]), "=r"(a[3]) : "r"(addr));
}
__device__ __forceinline__ unsigned h2u(float lo, float hi) {
    __half2 h = __floats2half2_rn(lo, hi);
    return *(unsigned*)&h;
}

// Static device scratch.  Activations NHWC16: [n][chunk][h][w][16ch] fp16,
// stored as u32 (half2); 8 u32 per pixel per chunk.
__device__ unsigned g_x16[BATCH * 10 * HW * 8];
__device__ unsigned g_z1h[BATCH *  8 * HW * 8];
__device__ unsigned g_z2h[BATCH *  4 * HW * 8];
__device__ float    g_z3 [BATCH *  8 * HW];      // fp32 NCHW for VQ
__device__ unsigned g_qh [BATCH *  1 * HW * 8];  // ch 8..15 zeroed by VQ
__device__ unsigned g_y1h[BATCH *  4 * HW * 8];
__device__ unsigned g_y2h[BATCH *  8 * HW * 8];
// fp16 weights: [chunk16][tap 9][CO_PAD][slot 8]; slot s -> ci pair
// (2p, 2p+1), p = (s&1)?(s>>1)+4:(s>>1)  (matches mma B fragment k-order).
__device__ unsigned g_w_e1[10 * 9 * 128 * 8];
__device__ unsigned g_w_e2[ 8 * 9 *  64 * 8];
__device__ unsigned g_w_e3[ 4 * 9 *  16 * 8];
__device__ unsigned g_w_d1[ 1 * 9 *  64 * 8];
__device__ unsigned g_w_d2[ 4 * 9 * 128 * 8];
__device__ unsigned g_w_d3[ 8 * 9 * 160 * 8];
__device__ double   g_part[256];

// ---------------------------------------------------------------------------
__device__ void pack16(const float* __restrict__ w, unsigned* __restrict__ out,
                       int CIN, int COUT, int CO_PAD, int transposed, int idx) {
    int s     = idx & 7;
    int co    = (idx >> 3) % CO_PAD;
    int tap   = ((idx >> 3) / CO_PAD) % 9;
    int chunk = ((idx >> 3) / CO_PAD) / 9;
    int p     = (s & 1) ? (s >> 1) + 4 : (s >> 1);
    int ci0   = chunk * 16 + 2 * p, ci1 = ci0 + 1;
    float v0 = 0.f, v1 = 0.f;
    if (co < COUT) {
        if (transposed) {
            if (ci0 < CIN) v0 = w[((size_t)ci0 * COUT + co) * 9 + (8 - tap)];
            if (ci1 < CIN) v1 = w[((size_t)ci1 * COUT + co) * 9 + (8 - tap)];
        } else {
            if (ci0 < CIN) v0 = w[((size_t)co * CIN + ci0) * 9 + tap];
            if (ci1 < CIN) v1 = w[((size_t)co * CIN + ci1) * 9 + tap];
        }
    }
    out[idx] = h2u(v0, v1);
}

__global__ void pack_all(const float* e1w, const float* e2w, const float* e3w,
                         const float* d1w, const float* d2w, const float* d3w,
                         unsigned* we1, unsigned* we2, unsigned* we3,
                         unsigned* wd1, unsigned* wd2, unsigned* wd3) {
    int idx = blockIdx.x * 256 + threadIdx.x;
    if (idx < 92160) { pack16(e1w, we1, 156, 128, 128, 0, idx); return; }
    idx -= 92160;
    if (idx < 36864) { pack16(e2w, we2, 128,  64,  64, 0, idx); return; }
    idx -= 36864;
    if (idx < 4608)  { pack16(e3w, we3,  64,   8,  16, 0, idx); return; }
    idx -= 4608;
    if (idx < 4608)  { pack16(d1w, wd1,   8,  64,  64, 1, idx); return; }
    idx -= 4608;
    if (idx < 36864) { pack16(d2w, wd2,  64, 128, 128, 1, idx); return; }
    idx -= 36864;
    if (idx < 92160) { pack16(d3w, wd3, 128, 156, 160, 1, idx); }
}

// x (fp32 NCHW, 156 ch) -> NHWC16 fp16, ch 156..159 zero.
__global__ void x_to_nhwc(const float* __restrict__ x, unsigned* __restrict__ x16) {
    int i = blockIdx.x * 256 + threadIdx.x;
    const int total = BATCH * 10 * HW;
    if (i >= total) return;
    int hw   = i & 16383;
    int rest = i >> 14;
    int c16  = rest % 10;
    int n    = rest / 10;
    float v[16];
#pragma unroll
    for (int j = 0; j < 16; j++) {
        int ch = c16 * 16 + j;
        v[j] = (ch < 156) ? x[((size_t)n * 156 + ch) * HW + hw] : 0.f;
    }
    uint4 o0, o1;
    o0.x = h2u(v[0], v[1]);   o0.y = h2u(v[2], v[3]);
    o0.z = h2u(v[4], v[5]);   o0.w = h2u(v[6], v[7]);
    o1.x = h2u(v[8], v[9]);   o1.y = h2u(v[10], v[11]);
    o1.z = h2u(v[12], v[13]); o1.w = h2u(v[14], v[15]);
    uint4* dst = (uint4*)x16 + ((size_t)i) * 2;
    dst[0] = o0; dst[1] = o1;
}

__device__ __forceinline__ float apply_act(float v, int ACT) {
    if (ACT == 1) return fmaxf(v, 0.f);
    if (ACT == 2) return 1.f / (1.f + __expf(-v));
    return v;
}

// ---------------------------------------------------------------------------
// fp16 tensor-core 3x3 same-conv (mma.sync m16n8k16) on NHWC16.
// Block = (n, row h, MT co).  8 warps: wm=warp&3 -> 32-px span,
// wn=warp>>2 -> MT/2 co.  smem slab [3 rows][130 px][16ch], px stride 48B
// (16B-aligned for ldmatrix, bank-conflict-free).  A fragment = 1 ldmatrix.x4.
// B via __ldg (L1-resident).  Register-prefetch double buffer, 1 barrier/chunk.
// ---------------------------------------------------------------------------
template<int CIN, int COUT, int MT, int ACT, int CO_OFF, int CO_PAD, bool OUTF16, int NBLK>
__global__ __launch_bounds__(256, NBLK)
void convmma16(const unsigned* __restrict__ in, const unsigned* __restrict__ mw,
               const float* __restrict__ bias, void* __restrict__ outp) {
    constexpr int CHUNKS = (CIN + 15) / 16;
    constexpr int ROWW   = 130 * 12;         // u32 words per slab row (px stride 12)
    constexpr int BUFW   = 3 * ROWW;         // 4680 words = 18720 B
    constexpr int NT     = MT / 16;

    __shared__ unsigned s_in[2 * BUFW];      // 37440 B

    const int n    = blockIdx.z;
    const int h    = blockIdx.x;
    const int cob0 = CO_OFF + blockIdx.y * MT;
    const int tid  = threadIdx.x;
    const int lane = tid & 31;
    const int warp = tid >> 5;
    const int wm   = warp & 3;
    const int wn   = warp >> 2;
    const int r4   = lane & 3;
    const int r4h  = lane >> 2;
    const int pxb  = wm * 32;
    const int col  = wn * (MT / 2);

    const uint4* inN4 = (const uint4*)in + (size_t)n * CHUNKS * (HW * 2);

    // zero halo pixels (px_s 0 and 129, both 16B halves, 3 rows, 2 buffers)
    if (tid < 96) {
        int w  = tid & 7;
        int px = ((tid >> 3) & 1) ? 129 : 0;
        int r  = (tid >> 4) % 3;
        int b  = tid / 48;
        s_in[b * BUFW + r * ROWW + px * 12 + w] = 0u;
    }

    // staging slots: 768 uint4 = 3 per thread; warp-local (px, half) mapping
    int sm_off[3], g_off[3]; bool rowok[3];
#pragma unroll
    for (int jj = 0; jj < 3; jj++) {
        int j    = jj * 256 + tid;
        int row  = j >> 8;
        int i    = j & 255;
        int px   = ((i >> 5) << 4) + (i & 15);
        int half = (i >> 4) & 1;
        int gh   = h - 1 + row;
        rowok[jj]  = (gh >= 0 && gh < 128);
        sm_off[jj] = row * ROWW + (px + 1) * 12 + half * 4;
        g_off[jj]  = (rowok[jj] ? gh : 0) * 256 + px * 2 + half;
    }

    float C[2][NT][4];
#pragma unroll
    for (int mt = 0; mt < 2; mt++)
#pragma unroll
        for (int nt = 0; nt < NT; nt++)
#pragma unroll
            for (int k = 0; k < 4; k++) C[mt][nt][k] = 0.f;

    const unsigned sbase = (unsigned)__cvta_generic_to_shared((void*)s_in);
    const unsigned athr  = sbase + (unsigned)((pxb + (lane & 15)) * 48) + (lane & 16);

    uint4 pf[3];
#pragma unroll
    for (int jj = 0; jj < 3; jj++)
        pf[jj] = rowok[jj] ? inN4[g_off[jj]] : make_uint4(0, 0, 0, 0);

    for (int chunk = 0; chunk < CHUNKS; chunk++) {
        unsigned* buf = s_in + (chunk & 1) * BUFW;
#pragma unroll
        for (int jj = 0; jj < 3; jj++) *(uint4*)(buf + sm_off[jj]) = pf[jj];
        __syncthreads();

        if (chunk + 1 < CHUNKS) {
#pragma unroll
            for (int jj = 0; jj < 3; jj++)
                pf[jj] = rowok[jj]
                       ? inN4[(size_t)(chunk + 1) * (HW * 2) + g_off[jj]]
                       : make_uint4(0, 0, 0, 0);
        }

        const unsigned abuf = athr + (chunk & 1) * (BUFW * 4);
        const unsigned* wc = mw + (((size_t)chunk * 9) * CO_PAD + cob0 + col + r4h) * 8 + r4 * 2;

#pragma unroll
        for (int dh = 0; dh < 3; dh++) {
#pragma unroll
            for (int dw = 0; dw < 3; dw++) {
                const int tap = dh * 3 + dw;
                unsigned a0[4], a1[4];
                ldsm4(a0, abuf + dh * (ROWW * 4) + dw * 48);
                ldsm4(a1, abuf + dh * (ROWW * 4) + (dw + 16) * 48);
#pragma unroll
                for (int nt = 0; nt < NT; nt++) {
                    uint2 b = __ldg((const uint2*)(wc + ((size_t)tap * CO_PAD + nt * 8) * 8));
                    mma_f16(C[0][nt], a0, b);
                    mma_f16(C[1][nt], a1, b);
                }
            }
        }
    }

    // epilogue: c0 (px, co) c1 (px, co+1) c2 (px+8, co) c3 (px+8, co+1)
#pragma unroll
    for (int mt = 0; mt < 2; mt++) {
#pragma unroll
        for (int nt = 0; nt < NT; nt++) {
            int px = pxb + mt * 16 + r4h;
            int co = cob0 + col + nt * 8 + 2 * r4;
            if (OUTF16) {
                float b0 = bias[co], b1 = bias[co + 1];
                unsigned* op = (unsigned*)outp
                    + (((size_t)n * (COUT / 16) + (co >> 4)) * HW + h * 128 + px) * 8
                    + ((co & 15) >> 1);
                op[0]  = h2u(apply_act(C[mt][nt][0] + b0, ACT),
                             apply_act(C[mt][nt][1] + b1, ACT));
                op[64] = h2u(apply_act(C[mt][nt][2] + b0, ACT),
                             apply_act(C[mt][nt][3] + b1, ACT));
            } else {
#pragma unroll
                for (int half = 0; half < 2; half++) {
                    if (co + half < COUT) {
                        float b = bias[co + half];
                        float* op = (float*)outp + ((size_t)n * COUT + co + half) * HW
                                  + h * 128 + px;
                        op[0] = apply_act(C[mt][nt][half] + b, ACT);
                        op[8] = apply_act(C[mt][nt][2 + half] + b, ACT);
                    }
                }
            }
        }
    }
}

// ---------------------------------------------------------------------------
// Vector quantizer.  Vector = 8 consecutive W pixels of one channel.  Thread
// handles 4 channels (4cg..4cg+3) of one (n, h, wgroup) -> writes q NHWC16
// directly (uint2 data + uint2 zeros for ch 8..15).  Loss exact fp32.
// ---------------------------------------------------------------------------
__global__ __launch_bounds__(256)
void vq_kernel(const float* __restrict__ z, const float* __restrict__ emb,
               unsigned* __restrict__ q16, double* __restrict__ part) {
    __shared__ float  s_e[512 * 8];
    __shared__ float  s_hn[512];
    __shared__ double s_red[256];

    const int tid = threadIdx.x;
    for (int i = tid; i < 4096; i += 256) s_e[i] = emb[i];
    __syncthreads();
    for (int k = tid; k < 512; k += 256) {
        float s = 0.f;
#pragma unroll
        for (int j = 0; j < 8; j++) { float e = s_e[k * 8 + j]; s += e * e; }
        s_hn[k] = 0.5f * s;
    }
    __syncthreads();

    const int ti = blockIdx.x * 256 + tid;
    const int wg = ti & 15;
    const int hh = (ti >> 4) & 127;
    const int cg = (ti >> 11) & 1;
    const int nn = ti >> 12;

    float v[4][8];
#pragma unroll
    for (int e = 0; e < 4; e++) {
        int vi = (((nn * 8 + 4 * cg + e) * 128) + hh) * 16 + wg;
        float4 a = ((const float4*)z)[vi * 2];
        float4 b = ((const float4*)z)[vi * 2 + 1];
        v[e][0] = a.x; v[e][1] = a.y; v[e][2] = a.z; v[e][3] = a.w;
        v[e][4] = b.x; v[e][5] = b.y; v[e][6] = b.z; v[e][7] = b.w;
    }

    float best[4] = {3.4e38f, 3.4e38f, 3.4e38f, 3.4e38f};
    int   bk[4]   = {0, 0, 0, 0};
    for (int k = 0; k < 512; k++) {
        float e0 = s_e[k * 8 + 0], e1 = s_e[k * 8 + 1], e2 = s_e[k * 8 + 2], e3 = s_e[k * 8 + 3];
        float e4 = s_e[k * 8 + 4], e5 = s_e[k * 8 + 5], e6 = s_e[k * 8 + 6], e7 = s_e[k * 8 + 7];
        float hn = s_hn[k];
#pragma unroll
        for (int u = 0; u < 4; u++) {
            float dot = e0 * v[u][0] + e1 * v[u][1] + e2 * v[u][2] + e3 * v[u][3]
                      + e4 * v[u][4] + e5 * v[u][5] + e6 * v[u][6] + e7 * v[u][7];
            float sc = hn - dot;
            if (sc < best[u]) { best[u] = sc; bk[u] = k; }
        }
    }

    float sq = 0.f;
#pragma unroll
    for (int u = 0; u < 4; u++)
#pragma unroll
        for (int j = 0; j < 8; j++) {
            float d = s_e[bk[u] * 8 + j] - v[u][j];
            sq += d * d;
        }

    // write q NHWC16: ch (4cg..4cg+3) data + zeros for ch (8+4cg..11+4cg)
    size_t pxbase = (size_t)nn * HW + hh * 128 + wg * 8;
#pragma unroll
    for (int p = 0; p < 8; p++) {
        uint2 d;
        d.x = h2u(s_e[bk[0] * 8 + p], s_e[bk[1] * 8 + p]);
        d.y = h2u(s_e[bk[2] * 8 + p], s_e[bk[3] * 8 + p]);
        unsigned* qp = q16 + (pxbase + p) * 8 + cg * 2;
        *(uint2*)qp       = d;
        *(uint2*)(qp + 4) = make_uint2(0u, 0u);
    }

    s_red[tid] = (double)sq;
    __syncthreads();
    for (int o = 128; o > 0; o >>= 1) {
        if (tid < o) s_red[tid] += s_red[tid + o];
        __syncthreads();
    }
    if (tid == 0) part[blockIdx.x] = s_red[0];
}

__global__ void finalize_loss(const double* __restrict__ part, float* __restrict__ outp) {
    __shared__ double s[256];
    int tid = threadIdx.x;
    s[tid] = part[tid];
    __syncthreads();
    for (int o = 128; o > 0; o >>= 1) {
        if (tid < o) s[tid] += s[tid + o];
        __syncthreads();
    }
    if (tid == 0) *outp = (float)(1.25 * s[0] / 2097152.0);
}

// ---------------------------------------------------------------------------
extern "C" void kernel_launch(void* const* d_in, const int* in_sizes, int n_in,
                              void* d_out, int out_size) {
    (void)in_sizes; (void)n_in;
    const float* x   = (const float*)d_in[0];
    const float* e1w = (const float*)d_in[1];
    const float* e1b = (const float*)d_in[2];
    const float* e2w = (const float*)d_in[3];
    const float* e2b = (const float*)d_in[4];
    const float* e3w = (const float*)d_in[5];
    const float* e3b = (const float*)d_in[6];
    const float* emb = (const float*)d_in[7];
    const float* d1w = (const float*)d_in[8];
    const float* d1b = (const float*)d_in[9];
    const float* d2w = (const float*)d_in[10];
    const float* d2b = (const float*)d_in[11];
    const float* d3w = (const float*)d_in[12];
    const float* d3b = (const float*)d_in[13];
    float* out = (float*)d_out;

    void *x16, *z1h, *z2h, *z3, *qh, *y1h, *y2h, *part;
    void *we1, *we2, *we3, *wd1, *wd2, *wd3;
    cudaGetSymbolAddress(&x16, g_x16);
    cudaGetSymbolAddress(&z1h, g_z1h);
    cudaGetSymbolAddress(&z2h, g_z2h);
    cudaGetSymbolAddress(&z3,  g_z3);
    cudaGetSymbolAddress(&qh,  g_qh);
    cudaGetSymbolAddress(&y1h, g_y1h);
    cudaGetSymbolAddress(&y2h, g_y2h);
    cudaGetSymbolAddress(&we1, g_w_e1);
    cudaGetSymbolAddress(&we2, g_w_e2);
    cudaGetSymbolAddress(&we3, g_w_e3);
    cudaGetSymbolAddress(&wd1, g_w_d1);
    cudaGetSymbolAddress(&wd2, g_w_d2);
    cudaGetSymbolAddress(&wd3, g_w_d3);
    cudaGetSymbolAddress(&part, g_part);

    // ---- weight packing + x conversion
    pack_all<<<(267264 + 255) / 256, 256>>>(
        e1w, e2w, e3w, d1w, d2w, d3w,
        (unsigned*)we1, (unsigned*)we2, (unsigned*)we3,
        (unsigned*)wd1, (unsigned*)wd2, (unsigned*)wd3);
    x_to_nhwc<<<(BATCH * 10 * HW + 255) / 256, 256>>>(x, (unsigned*)x16);

    // encoder (fp16 tensor path, NHWC16)
    convmma16<156, 128, 128, 1, 0, 128, true, 2>
        <<<dim3(128, 1, 16), 256>>>((unsigned*)x16, (unsigned*)we1, e1b, z1h);
    convmma16<128,  64,  64, 1, 0,  64, true, 3>
        <<<dim3(128, 1, 16), 256>>>((unsigned*)z1h, (unsigned*)we2, e2b, z2h);
    convmma16< 64,   8,  16, 1, 0,  16, false, 3>
        <<<dim3(128, 1, 16), 256>>>((unsigned*)z2h, (unsigned*)we3, e3b, z3);

    // vector quantizer + loss partials (exact fp32; q emitted NHWC16)
    vq_kernel<<<256, 256>>>((const float*)z3, emb, (unsigned*)qh, (double*)part);

    // decoder (fp16 tensor path, NHWC16)
    convmma16<  8,  64,  64, 1, 0,  64, true, 3>
        <<<dim3(128, 1, 16), 256>>>((unsigned*)qh,  (unsigned*)wd1, d1b, y1h);
    convmma16< 64, 128, 128, 1, 0, 128, true, 2>
        <<<dim3(128, 1, 16), 256>>>((unsigned*)y1h, (unsigned*)wd2, d2b, y2h);
    convmma16<128, 156,  80, 2, 0, 160, false, 2>
        <<<dim3(128, 2, 16), 256>>>((unsigned*)y2h, (unsigned*)wd3, d3b, out);

    finalize_loss<<<1, 256>>>((const double*)part, out + (out_size - 1));
}